// round 1
// baseline (speedup 1.0000x reference)
#include <cuda_runtime.h>
#include <math.h>

#define D_MODEL   1024
#define NUM_HEADS 16
#define HEAD_DIM  64
#define BATCH     2
#define SEQ       2048
#define M_TOT     (BATCH * SEQ)   // 4096

// ---------------- scratch (device globals; no allocation) ----------------
__device__ float g_q [BATCH * NUM_HEADS * SEQ * HEAD_DIM];   // 16 MB
__device__ float g_k [BATCH * NUM_HEADS * SEQ * HEAD_DIM];   // 16 MB
__device__ float g_v [BATCH * NUM_HEADS * SEQ * HEAD_DIM];   // 16 MB
__device__ float g_ao[M_TOT * D_MODEL];                      // 16 MB

// ---------------- GEMM: out = X @ W^T + bias ----------------
// X: [4096, 1024] row-major, W: [1024, 1024] row-major (we dot rows of W).
// head_layout=1: scatter to [B,H,S,hd]; head_layout=0: write [M, N] row-major.
__global__ __launch_bounds__(256) void gemm_proj(
    const float* __restrict__ X, const float* __restrict__ W,
    const float* __restrict__ bias, float* __restrict__ out, int head_layout)
{
    __shared__ float As[16][65];   // [k][m], padded
    __shared__ float Bs[16][65];   // [k][n], padded

    const int tid = threadIdx.x;           // 0..255
    const int tx  = tid & 15;
    const int ty  = tid >> 4;
    const int m0  = blockIdx.y * 64;
    const int n0  = blockIdx.x * 64;

    float acc[4][4];
    #pragma unroll
    for (int i = 0; i < 4; i++)
        #pragma unroll
        for (int j = 0; j < 4; j++) acc[i][j] = 0.f;

    for (int kt = 0; kt < D_MODEL; kt += 16) {
        #pragma unroll
        for (int jj = 0; jj < 4; jj++) {
            int i = tid + 256 * jj;         // 0..1023
            int r = i >> 4, c = i & 15;
            As[c][r] = X[(m0 + r) * D_MODEL + kt + c];
            Bs[c][r] = W[(n0 + r) * D_MODEL + kt + c];
        }
        __syncthreads();

        #pragma unroll
        for (int kk = 0; kk < 16; kk++) {
            float a[4], b[4];
            #pragma unroll
            for (int i = 0; i < 4; i++) a[i] = As[kk][ty * 4 + i];
            #pragma unroll
            for (int j = 0; j < 4; j++) b[j] = Bs[kk][tx * 4 + j];
            #pragma unroll
            for (int i = 0; i < 4; i++)
                #pragma unroll
                for (int j = 0; j < 4; j++)
                    acc[i][j] = fmaf(a[i], b[j], acc[i][j]);
        }
        __syncthreads();
    }

    #pragma unroll
    for (int i = 0; i < 4; i++) {
        int m = m0 + ty * 4 + i;
        int b_ = m >> 11;          // m / 2048
        int s  = m & 2047;
        #pragma unroll
        for (int j = 0; j < 4; j++) {
            int n = n0 + tx * 4 + j;
            float v = acc[i][j] + bias[n];
            if (head_layout) {
                int h = n >> 6, d = n & 63;
                out[(((b_ * NUM_HEADS + h) * SEQ) + s) * HEAD_DIM + d] = v;
            } else {
                out[m * D_MODEL + n] = v;
            }
        }
    }
}

// ---------------- Flash attention (fp32, online softmax) ----------------
// Grid: (SEQ/64, B*H). Block: 256 threads.
// Per block: 64 queries x full K/V sweep in 64-wide tiles.
// Dynamic smem layout (floats):
//   Qs   [64][64]       at 0       (4096)
//   KsPs [64][65]       at 4096    (4160)   (K tile, reused as P tile)
//   Vs   [64][64]       at 8256    (4096)
// total 12352 floats = 49408 bytes
__global__ __launch_bounds__(256) void flash_attn(
    const float* __restrict__ Q, const float* __restrict__ K,
    const float* __restrict__ V, float* __restrict__ O)
{
    extern __shared__ float sm[];
    float* Qs   = sm;            // stride 64
    float* KsPs = sm + 4096;     // stride 65
    float* Vs   = sm + 8256;     // stride 64

    const int tid = threadIdx.x;
    const int tx  = tid & 15;
    const int ty  = tid >> 4;
    const int bh  = blockIdx.y;          // 0..31
    const int b_  = bh >> 4;
    const int h   = bh & 15;
    const int q0  = blockIdx.x * 64;
    const float scale = 0.125f;          // 1/sqrt(64)

    const float* Qb = Q + (size_t)bh * SEQ * HEAD_DIM;
    const float* Kb = K + (size_t)bh * SEQ * HEAD_DIM;
    const float* Vb = V + (size_t)bh * SEQ * HEAD_DIM;

    // load Q tile (pre-scaled)
    #pragma unroll
    for (int it = 0; it < 16; it++) {
        int i = tid + it * 256;
        int r = i >> 6, c = i & 63;
        Qs[r * 64 + c] = Qb[(q0 + r) * HEAD_DIM + c] * scale;
    }

    float m_i[4], l_i[4], o[4][4];
    #pragma unroll
    for (int i = 0; i < 4; i++) {
        m_i[i] = -1e30f;
        l_i[i] = 0.f;
        #pragma unroll
        for (int j = 0; j < 4; j++) o[i][j] = 0.f;
    }
    __syncthreads();

    for (int k0 = 0; k0 < SEQ; k0 += 64) {
        // load K, V tiles
        #pragma unroll
        for (int it = 0; it < 16; it++) {
            int i = tid + it * 256;
            int r = i >> 6, c = i & 63;
            KsPs[r * 65 + c] = Kb[(k0 + r) * HEAD_DIM + c];
            Vs  [r * 64 + c] = Vb[(k0 + r) * HEAD_DIM + c];
        }
        __syncthreads();

        // scores: s[i][j] = Qrow(ty*4+i) . Krow(tx*4+j)
        float s[4][4];
        #pragma unroll
        for (int i = 0; i < 4; i++)
            #pragma unroll
            for (int j = 0; j < 4; j++) s[i][j] = 0.f;

        #pragma unroll 8
        for (int d = 0; d < 64; d++) {
            float a[4], b[4];
            #pragma unroll
            for (int i = 0; i < 4; i++) a[i] = Qs[(ty * 4 + i) * 64 + d];
            #pragma unroll
            for (int j = 0; j < 4; j++) b[j] = KsPs[(tx * 4 + j) * 65 + d];
            #pragma unroll
            for (int i = 0; i < 4; i++)
                #pragma unroll
                for (int j = 0; j < 4; j++)
                    s[i][j] = fmaf(a[i], b[j], s[i][j]);
        }

        // everyone done reading K before we overwrite it with P
        __syncthreads();

        // online softmax per row (row owned by 16 lanes sharing ty)
        #pragma unroll
        for (int i = 0; i < 4; i++) {
            float mt = fmaxf(fmaxf(s[i][0], s[i][1]), fmaxf(s[i][2], s[i][3]));
            #pragma unroll
            for (int off = 8; off >= 1; off >>= 1)
                mt = fmaxf(mt, __shfl_xor_sync(0xffffffffu, mt, off, 16));
            float mnew  = fmaxf(m_i[i], mt);
            float alpha = __expf(m_i[i] - mnew);
            m_i[i] = mnew;

            float lsum = 0.f;
            #pragma unroll
            for (int j = 0; j < 4; j++) {
                s[i][j] = __expf(s[i][j] - mnew);
                lsum += s[i][j];
            }
            #pragma unroll
            for (int off = 8; off >= 1; off >>= 1)
                lsum += __shfl_xor_sync(0xffffffffu, lsum, off, 16);
            l_i[i] = l_i[i] * alpha + lsum;

            #pragma unroll
            for (int j = 0; j < 4; j++) {
                o[i][j] *= alpha;
                KsPs[(ty * 4 + i) * 65 + (tx * 4 + j)] = s[i][j];  // P tile
            }
        }
        __syncthreads();

        // o += P @ V : o[i][j] += sum_kk P[row][kk] * V[kk][tx*4+j]
        #pragma unroll 8
        for (int kk = 0; kk < 64; kk++) {
            float a[4], b[4];
            #pragma unroll
            for (int i = 0; i < 4; i++) a[i] = KsPs[(ty * 4 + i) * 65 + kk];
            #pragma unroll
            for (int j = 0; j < 4; j++) b[j] = Vs[kk * 64 + tx * 4 + j];
            #pragma unroll
            for (int i = 0; i < 4; i++)
                #pragma unroll
                for (int j = 0; j < 4; j++)
                    o[i][j] = fmaf(a[i], b[j], o[i][j]);
        }
        __syncthreads();
    }

    // finalize, write to [B, S, D] layout
    #pragma unroll
    for (int i = 0; i < 4; i++) {
        float inv_l = 1.f / l_i[i];
        int srow = q0 + ty * 4 + i;
        #pragma unroll
        for (int j = 0; j < 4; j++) {
            int d = tx * 4 + j;
            O[(size_t)(b_ * SEQ + srow) * D_MODEL + h * HEAD_DIM + d] = o[i][j] * inv_l;
        }
    }
}

// ---------------- launcher ----------------
extern "C" void kernel_launch(void* const* d_in, const int* in_sizes, int n_in,
                              void* d_out, int out_size)
{
    const float* x  = (const float*)d_in[0];
    const float* Wq = (const float*)d_in[1];
    const float* bq = (const float*)d_in[2];
    const float* Wk = (const float*)d_in[3];
    const float* bk = (const float*)d_in[4];
    const float* Wv = (const float*)d_in[5];
    const float* bv = (const float*)d_in[6];
    const float* Wo = (const float*)d_in[7];
    const float* bo = (const float*)d_in[8];
    float* out = (float*)d_out;

    float *pq, *pk, *pv, *pao;
    cudaGetSymbolAddress((void**)&pq,  g_q);
    cudaGetSymbolAddress((void**)&pk,  g_k);
    cudaGetSymbolAddress((void**)&pv,  g_v);
    cudaGetSymbolAddress((void**)&pao, g_ao);

    static bool configured = false;
    if (!configured) {
        cudaFuncSetAttribute(flash_attn,
                             cudaFuncAttributeMaxDynamicSharedMemorySize, 49408);
        configured = true;
    }

    dim3 ggrid(D_MODEL / 64, M_TOT / 64);   // (16, 64)
    gemm_proj<<<ggrid, 256>>>(x, Wq, bq, pq, 1);
    gemm_proj<<<ggrid, 256>>>(x, Wk, bk, pk, 1);
    gemm_proj<<<ggrid, 256>>>(x, Wv, bv, pv, 1);

    dim3 agrid(SEQ / 64, BATCH * NUM_HEADS); // (32, 32)
    flash_attn<<<agrid, 256, 49408>>>(pq, pk, pv, pao);

    gemm_proj<<<ggrid, 256>>>(pao, Wo, bo, out, 0);
}

// round 3
// speedup vs baseline: 1.9765x; 1.9765x over previous
#include <cuda_runtime.h>
#include <math.h>
#include <stdint.h>

#define D_MODEL   1024
#define NUM_HEADS 16
#define HEAD_DIM  64
#define BATCH     2
#define SEQ       2048
#define M_TOT     (BATCH * SEQ)   // 4096

// ---------------- scratch (device globals; no allocation) ----------------
__device__ float g_q [BATCH * NUM_HEADS * SEQ * HEAD_DIM];   // 16 MB
__device__ float g_k [BATCH * NUM_HEADS * SEQ * HEAD_DIM];   // 16 MB
__device__ float g_v [BATCH * NUM_HEADS * SEQ * HEAD_DIM];   // 16 MB
__device__ float g_ao[M_TOT * D_MODEL];                      // 16 MB (tf32-rounded)
__device__ float g_xt[M_TOT * D_MODEL];                      // 16 MB x in tf32
__device__ float g_wq[D_MODEL * D_MODEL];                    // 4 MB each
__device__ float g_wk[D_MODEL * D_MODEL];
__device__ float g_wv[D_MODEL * D_MODEL];
__device__ float g_wo[D_MODEL * D_MODEL];

// ======================= helpers =======================
static __device__ __forceinline__ uint32_t smem_u32(const void* p) {
    uint32_t a;
    asm("{ .reg .u64 t; cvta.to.shared.u64 t, %1; cvt.u32.u64 %0, t; }"
        : "=r"(a) : "l"(p));
    return a;
}
static __device__ __forceinline__ float tf32r(float x) {
    uint32_t u;
    asm("cvt.rna.tf32.f32 %0, %1;" : "=r"(u) : "f"(x));
    return __uint_as_float(u);
}
static __device__ __forceinline__ void cp16(uint32_t dst, const void* src) {
    asm volatile("cp.async.ca.shared.global [%0], [%1], 16;"
                 :: "r"(dst), "l"(src) : "memory");
}
#define CP_COMMIT() asm volatile("cp.async.commit_group;" ::: "memory")
#define CP_WAIT(n)  asm volatile("cp.async.wait_group %0;" :: "n"(n) : "memory")

static __device__ __forceinline__ void mma_tf32(
    float& d0, float& d1, float& d2, float& d3,
    uint32_t a0, uint32_t a1, uint32_t a2, uint32_t a3,
    uint32_t b0, uint32_t b1)
{
    asm volatile(
        "mma.sync.aligned.m16n8k8.row.col.f32.tf32.tf32.f32 "
        "{%0,%1,%2,%3}, {%4,%5,%6,%7}, {%8,%9}, {%0,%1,%2,%3};"
        : "+f"(d0), "+f"(d1), "+f"(d2), "+f"(d3)
        : "r"(a0), "r"(a1), "r"(a2), "r"(a3), "r"(b0), "r"(b1));
}

// ======================= tf32 round-convert =======================
__global__ __launch_bounds__(256) void cvt_tf32(
    const float4* __restrict__ in, float4* __restrict__ out, int n4)
{
    int i = blockIdx.x * 256 + threadIdx.x;
    if (i < n4) {
        float4 v = in[i];
        v.x = tf32r(v.x); v.y = tf32r(v.y); v.z = tf32r(v.z); v.w = tf32r(v.w);
        out[i] = v;
    }
}

// ======================= mma.sync tf32 GEMM =======================
// D[M=4096, N=1024] = A @ B^T + bias.  A:[M,1024] tf32, B:[N,1024] tf32 (K-major).
// Block tile 128x128x32, 8 warps (2x4), warp tile 64x32. cp.async double buffer.
// Smem rows padded to 36 floats: bank = (36r+c)%32 = (4r+c)%32 — conflict-free
// for the 8-row x 4-col fragment footprint, and 16B-aligned rows for cp.async.
#define GS_ROW   36
#define GS_BUF   (128 * GS_ROW)              // 4608 floats per buffer
#define GEMM_SMEM (4 * GS_BUF * 4)           // A[2] + B[2] = 73728 bytes

__global__ __launch_bounds__(256, 2) void gemm_mma(
    const float* __restrict__ A, const float* __restrict__ B,
    const float* __restrict__ bias, float* __restrict__ out, int head_layout)
{
    extern __shared__ __align__(16) float smem[];
    const uint32_t sbase = smem_u32(smem);

    const int tid  = threadIdx.x;
    const int lane = tid & 31;
    const int wid  = tid >> 5;
    const int wm   = wid & 1;        // 0..1  -> 64 rows each
    const int wn   = wid >> 1;       // 0..3  -> 32 cols each
    const int m0   = blockIdx.y * 128;
    const int n0   = blockIdx.x * 128;
    const int gr   = lane >> 2;      // group row 0..7
    const int gc   = lane & 3;       // group col 0..3

    float d[4][4][4];
    #pragma unroll
    for (int mt = 0; mt < 4; mt++)
        #pragma unroll
        for (int nt = 0; nt < 4; nt++)
            #pragma unroll
            for (int r = 0; r < 4; r++) d[mt][nt][r] = 0.f;

    // async load one 128x32 tile pair into buffer `buf`
    auto load_tile = [&](int kt, int buf) {
        #pragma unroll
        for (int it = 0; it < 4; it++) {
            int id = tid + it * 256;       // 0..1023
            int r  = id >> 3;
            int ch = (id & 7) * 4;
            uint32_t da = sbase + (uint32_t)(buf * GS_BUF + r * GS_ROW + ch) * 4u;
            cp16(da, A + (size_t)(m0 + r) * D_MODEL + kt + ch);
            uint32_t db = sbase + (uint32_t)((2 + buf) * GS_BUF + r * GS_ROW + ch) * 4u;
            cp16(db, B + (size_t)(n0 + r) * D_MODEL + kt + ch);
        }
    };

    load_tile(0, 0);
    CP_COMMIT();

    for (int t = 0; t < 32; t++) {
        if (t + 1 < 32) {
            load_tile((t + 1) * 32, (t + 1) & 1);
            CP_COMMIT();
            CP_WAIT(1);
        } else {
            CP_WAIT(0);
        }
        __syncthreads();

        const float* Asb = smem + (t & 1) * GS_BUF;
        const float* Bsb = smem + (2 + (t & 1)) * GS_BUF;

        #pragma unroll
        for (int ks = 0; ks < 4; ks++) {
            const int kc = ks * 8 + gc;
            uint32_t a[4][4];
            #pragma unroll
            for (int mt = 0; mt < 4; mt++) {
                int r = wm * 64 + mt * 16 + gr;
                a[mt][0] = __float_as_uint(Asb[r * GS_ROW + kc]);
                a[mt][1] = __float_as_uint(Asb[(r + 8) * GS_ROW + kc]);
                a[mt][2] = __float_as_uint(Asb[r * GS_ROW + kc + 4]);
                a[mt][3] = __float_as_uint(Asb[(r + 8) * GS_ROW + kc + 4]);
            }
            uint32_t b[4][2];
            #pragma unroll
            for (int nt = 0; nt < 4; nt++) {
                int n = wn * 32 + nt * 8 + gr;
                b[nt][0] = __float_as_uint(Bsb[n * GS_ROW + kc]);
                b[nt][1] = __float_as_uint(Bsb[n * GS_ROW + kc + 4]);
            }
            #pragma unroll
            for (int mt = 0; mt < 4; mt++)
                #pragma unroll
                for (int nt = 0; nt < 4; nt++)
                    mma_tf32(d[mt][nt][0], d[mt][nt][1], d[mt][nt][2], d[mt][nt][3],
                             a[mt][0], a[mt][1], a[mt][2], a[mt][3],
                             b[nt][0], b[nt][1]);
        }
        __syncthreads();
    }

    // epilogue: bias add, optional head scatter, float2 stores
    #pragma unroll
    for (int mt = 0; mt < 4; mt++) {
        int row = m0 + wm * 64 + mt * 16 + gr;
        #pragma unroll
        for (int nt = 0; nt < 4; nt++) {
            int col = n0 + wn * 32 + nt * 8 + 2 * gc;
            float2 bv = *(const float2*)&bias[col];
            float2 v0 = make_float2(d[mt][nt][0] + bv.x, d[mt][nt][1] + bv.y);
            float2 v1 = make_float2(d[mt][nt][2] + bv.x, d[mt][nt][3] + bv.y);
            if (head_layout) {
                int h = col >> 6, dd = col & 63;
                int b0_ = row >> 11, s0 = row & 2047;
                int b1_ = (row + 8) >> 11, s1 = (row + 8) & 2047;
                *(float2*)&out[(((size_t)(b0_ * NUM_HEADS + h) * SEQ) + s0) * HEAD_DIM + dd] = v0;
                *(float2*)&out[(((size_t)(b1_ * NUM_HEADS + h) * SEQ) + s1) * HEAD_DIM + dd] = v1;
            } else {
                *(float2*)&out[(size_t)row * D_MODEL + col] = v0;
                *(float2*)&out[(size_t)(row + 8) * D_MODEL + col] = v1;
            }
        }
    }
}

// ---------------- Flash attention (fp32, online softmax) ----------------
__global__ __launch_bounds__(256) void flash_attn(
    const float* __restrict__ Q, const float* __restrict__ K,
    const float* __restrict__ V, float* __restrict__ O)
{
    extern __shared__ float smf[];
    float* Qs   = smf;            // stride 64
    float* KsPs = smf + 4096;     // stride 65
    float* Vs   = smf + 8256;     // stride 64

    const int tid = threadIdx.x;
    const int tx  = tid & 15;
    const int ty  = tid >> 4;
    const int bh  = blockIdx.y;
    const int b_  = bh >> 4;
    const int h   = bh & 15;
    const int q0  = blockIdx.x * 64;
    const float scale = 0.125f;

    const float* Qb = Q + (size_t)bh * SEQ * HEAD_DIM;
    const float* Kb = K + (size_t)bh * SEQ * HEAD_DIM;
    const float* Vb = V + (size_t)bh * SEQ * HEAD_DIM;

    #pragma unroll
    for (int it = 0; it < 16; it++) {
        int i = tid + it * 256;
        int r = i >> 6, c = i & 63;
        Qs[r * 64 + c] = Qb[(q0 + r) * HEAD_DIM + c] * scale;
    }

    float m_i[4], l_i[4], o[4][4];
    #pragma unroll
    for (int i = 0; i < 4; i++) {
        m_i[i] = -1e30f; l_i[i] = 0.f;
        #pragma unroll
        for (int j = 0; j < 4; j++) o[i][j] = 0.f;
    }
    __syncthreads();

    for (int k0 = 0; k0 < SEQ; k0 += 64) {
        #pragma unroll
        for (int it = 0; it < 16; it++) {
            int i = tid + it * 256;
            int r = i >> 6, c = i & 63;
            KsPs[r * 65 + c] = Kb[(k0 + r) * HEAD_DIM + c];
            Vs  [r * 64 + c] = Vb[(k0 + r) * HEAD_DIM + c];
        }
        __syncthreads();

        float s[4][4];
        #pragma unroll
        for (int i = 0; i < 4; i++)
            #pragma unroll
            for (int j = 0; j < 4; j++) s[i][j] = 0.f;

        #pragma unroll 8
        for (int d = 0; d < 64; d++) {
            float a[4], b[4];
            #pragma unroll
            for (int i = 0; i < 4; i++) a[i] = Qs[(ty * 4 + i) * 64 + d];
            #pragma unroll
            for (int j = 0; j < 4; j++) b[j] = KsPs[(tx * 4 + j) * 65 + d];
            #pragma unroll
            for (int i = 0; i < 4; i++)
                #pragma unroll
                for (int j = 0; j < 4; j++)
                    s[i][j] = fmaf(a[i], b[j], s[i][j]);
        }
        __syncthreads();

        #pragma unroll
        for (int i = 0; i < 4; i++) {
            float mt = fmaxf(fmaxf(s[i][0], s[i][1]), fmaxf(s[i][2], s[i][3]));
            #pragma unroll
            for (int off = 8; off >= 1; off >>= 1)
                mt = fmaxf(mt, __shfl_xor_sync(0xffffffffu, mt, off, 16));
            float mnew  = fmaxf(m_i[i], mt);
            float alpha = __expf(m_i[i] - mnew);
            m_i[i] = mnew;

            float lsum = 0.f;
            #pragma unroll
            for (int j = 0; j < 4; j++) {
                s[i][j] = __expf(s[i][j] - mnew);
                lsum += s[i][j];
            }
            #pragma unroll
            for (int off = 8; off >= 1; off >>= 1)
                lsum += __shfl_xor_sync(0xffffffffu, lsum, off, 16);
            l_i[i] = l_i[i] * alpha + lsum;

            #pragma unroll
            for (int j = 0; j < 4; j++) {
                o[i][j] *= alpha;
                KsPs[(ty * 4 + i) * 65 + (tx * 4 + j)] = s[i][j];
            }
        }
        __syncthreads();

        #pragma unroll 8
        for (int kk = 0; kk < 64; kk++) {
            float a[4], b[4];
            #pragma unroll
            for (int i = 0; i < 4; i++) a[i] = KsPs[(ty * 4 + i) * 65 + kk];
            #pragma unroll
            for (int j = 0; j < 4; j++) b[j] = Vs[kk * 64 + tx * 4 + j];
            #pragma unroll
            for (int i = 0; i < 4; i++)
                #pragma unroll
                for (int j = 0; j < 4; j++)
                    o[i][j] = fmaf(a[i], b[j], o[i][j]);
        }
        __syncthreads();
    }

    // finalize; round to tf32 so the output projection consumes directly
    #pragma unroll
    for (int i = 0; i < 4; i++) {
        float inv_l = 1.f / l_i[i];
        int srow = q0 + ty * 4 + i;
        #pragma unroll
        for (int j = 0; j < 4; j++) {
            int d = tx * 4 + j;
            O[(size_t)(b_ * SEQ + srow) * D_MODEL + h * HEAD_DIM + d] =
                tf32r(o[i][j] * inv_l);
        }
    }
}

// ======================= launcher =======================
extern "C" void kernel_launch(void* const* d_in, const int* in_sizes, int n_in,
                              void* d_out, int out_size)
{
    const float* x  = (const float*)d_in[0];
    const float* Wq = (const float*)d_in[1];
    const float* bq = (const float*)d_in[2];
    const float* Wk = (const float*)d_in[3];
    const float* bk = (const float*)d_in[4];
    const float* Wv = (const float*)d_in[5];
    const float* bv = (const float*)d_in[6];
    const float* Wo = (const float*)d_in[7];
    const float* bo = (const float*)d_in[8];
    float* out = (float*)d_out;

    static float *pq, *pk, *pv, *pao, *pxt, *pwq, *pwk, *pwv, *pwo;
    static bool inited = false;
    if (!inited) {
        cudaGetSymbolAddress((void**)&pq,  g_q);
        cudaGetSymbolAddress((void**)&pk,  g_k);
        cudaGetSymbolAddress((void**)&pv,  g_v);
        cudaGetSymbolAddress((void**)&pao, g_ao);
        cudaGetSymbolAddress((void**)&pxt, g_xt);
        cudaGetSymbolAddress((void**)&pwq, g_wq);
        cudaGetSymbolAddress((void**)&pwk, g_wk);
        cudaGetSymbolAddress((void**)&pwv, g_wv);
        cudaGetSymbolAddress((void**)&pwo, g_wo);
        cudaFuncSetAttribute(gemm_mma,
                             cudaFuncAttributeMaxDynamicSharedMemorySize, GEMM_SMEM);
        cudaFuncSetAttribute(flash_attn,
                             cudaFuncAttributeMaxDynamicSharedMemorySize, 49408);
        inited = true;
    }

    // tf32 round-convert X and the four weight matrices
    {
        int n4x = M_TOT * D_MODEL / 4;
        int n4w = D_MODEL * D_MODEL / 4;
        cvt_tf32<<<(n4x + 255) / 256, 256>>>((const float4*)x,  (float4*)pxt, n4x);
        cvt_tf32<<<(n4w + 255) / 256, 256>>>((const float4*)Wq, (float4*)pwq, n4w);
        cvt_tf32<<<(n4w + 255) / 256, 256>>>((const float4*)Wk, (float4*)pwk, n4w);
        cvt_tf32<<<(n4w + 255) / 256, 256>>>((const float4*)Wv, (float4*)pwv, n4w);
        cvt_tf32<<<(n4w + 255) / 256, 256>>>((const float4*)Wo, (float4*)pwo, n4w);
    }

    dim3 ggrid(D_MODEL / 128, M_TOT / 128);   // (8, 32)
    gemm_mma<<<ggrid, 256, GEMM_SMEM>>>(pxt, pwq, bq, pq, 1);
    gemm_mma<<<ggrid, 256, GEMM_SMEM>>>(pxt, pwk, bk, pk, 1);
    gemm_mma<<<ggrid, 256, GEMM_SMEM>>>(pxt, pwv, bv, pv, 1);

    dim3 agrid(SEQ / 64, BATCH * NUM_HEADS);  // (32, 32)
    flash_attn<<<agrid, 256, 49408>>>(pq, pk, pv, pao);

    gemm_mma<<<ggrid, 256, GEMM_SMEM>>>(pao, pwo, bo, out, 0);
}

// round 4
// speedup vs baseline: 4.4598x; 2.2565x over previous
#include <cuda_runtime.h>
#include <math.h>
#include <stdint.h>

#define D_MODEL   1024
#define NUM_HEADS 16
#define HEAD_DIM  64
#define BATCH     2
#define SEQ       2048
#define M_TOT     (BATCH * SEQ)   // 4096

// ---------------- scratch (device globals; no allocation) ----------------
__device__ float g_q [BATCH * NUM_HEADS * SEQ * HEAD_DIM];   // 16 MB (tf32)
__device__ float g_k [BATCH * NUM_HEADS * SEQ * HEAD_DIM];   // 16 MB (tf32)
__device__ float g_v [BATCH * NUM_HEADS * SEQ * HEAD_DIM];   // 16 MB (tf32)
__device__ float g_ao[M_TOT * D_MODEL];                      // 16 MB (tf32)
__device__ float g_xt[M_TOT * D_MODEL];                      // 16 MB x in tf32
__device__ float g_wq[D_MODEL * D_MODEL];                    // 4 MB each
__device__ float g_wk[D_MODEL * D_MODEL];
__device__ float g_wv[D_MODEL * D_MODEL];
__device__ float g_wo[D_MODEL * D_MODEL];

// ======================= helpers =======================
static __device__ __forceinline__ uint32_t smem_u32(const void* p) {
    uint32_t a;
    asm("{ .reg .u64 t; cvta.to.shared.u64 t, %1; cvt.u32.u64 %0, t; }"
        : "=r"(a) : "l"(p));
    return a;
}
static __device__ __forceinline__ float tf32r(float x) {
    uint32_t u;
    asm("cvt.rna.tf32.f32 %0, %1;" : "=r"(u) : "f"(x));
    return __uint_as_float(u);
}
static __device__ __forceinline__ float exp2a(float x) {
    float y;
    asm("ex2.approx.ftz.f32 %0, %1;" : "=f"(y) : "f"(x));
    return y;
}
static __device__ __forceinline__ void cp16(uint32_t dst, const void* src) {
    asm volatile("cp.async.ca.shared.global [%0], [%1], 16;"
                 :: "r"(dst), "l"(src) : "memory");
}
#define CP_COMMIT() asm volatile("cp.async.commit_group;" ::: "memory")
#define CP_WAIT(n)  asm volatile("cp.async.wait_group %0;" :: "n"(n) : "memory")

static __device__ __forceinline__ void mma_tf32(
    float& d0, float& d1, float& d2, float& d3,
    uint32_t a0, uint32_t a1, uint32_t a2, uint32_t a3,
    uint32_t b0, uint32_t b1)
{
    asm volatile(
        "mma.sync.aligned.m16n8k8.row.col.f32.tf32.tf32.f32 "
        "{%0,%1,%2,%3}, {%4,%5,%6,%7}, {%8,%9}, {%0,%1,%2,%3};"
        : "+f"(d0), "+f"(d1), "+f"(d2), "+f"(d3)
        : "r"(a0), "r"(a1), "r"(a2), "r"(a3), "r"(b0), "r"(b1));
}

// ======================= tf32 round-convert =======================
__global__ __launch_bounds__(256) void cvt_tf32(
    const float4* __restrict__ in, float4* __restrict__ out, int n4)
{
    int i = blockIdx.x * 256 + threadIdx.x;
    if (i < n4) {
        float4 v = in[i];
        v.x = tf32r(v.x); v.y = tf32r(v.y); v.z = tf32r(v.z); v.w = tf32r(v.w);
        out[i] = v;
    }
}

// ======================= mma.sync tf32 GEMM =======================
// D[M=4096, N=1024] = A @ B^T + bias.  Block 128x128x32, 8 warps, cp.async x2.
#define GS_ROW   36
#define GS_BUF   (128 * GS_ROW)
#define GEMM_SMEM (4 * GS_BUF * 4)           // 73728 bytes

__global__ __launch_bounds__(256, 2) void gemm_mma(
    const float* __restrict__ A, const float* __restrict__ B,
    const float* __restrict__ bias, float* __restrict__ out, int head_layout)
{
    extern __shared__ __align__(16) float smem[];
    const uint32_t sbase = smem_u32(smem);

    const int tid  = threadIdx.x;
    const int lane = tid & 31;
    const int wid  = tid >> 5;
    const int wm   = wid & 1;
    const int wn   = wid >> 1;
    const int m0   = blockIdx.y * 128;
    const int n0   = blockIdx.x * 128;
    const int gr   = lane >> 2;
    const int gc   = lane & 3;

    float d[4][4][4];
    #pragma unroll
    for (int mt = 0; mt < 4; mt++)
        #pragma unroll
        for (int nt = 0; nt < 4; nt++)
            #pragma unroll
            for (int r = 0; r < 4; r++) d[mt][nt][r] = 0.f;

    auto load_tile = [&](int kt, int buf) {
        #pragma unroll
        for (int it = 0; it < 4; it++) {
            int id = tid + it * 256;
            int r  = id >> 3;
            int ch = (id & 7) * 4;
            uint32_t da = sbase + (uint32_t)(buf * GS_BUF + r * GS_ROW + ch) * 4u;
            cp16(da, A + (size_t)(m0 + r) * D_MODEL + kt + ch);
            uint32_t db = sbase + (uint32_t)((2 + buf) * GS_BUF + r * GS_ROW + ch) * 4u;
            cp16(db, B + (size_t)(n0 + r) * D_MODEL + kt + ch);
        }
    };

    load_tile(0, 0);
    CP_COMMIT();

    for (int t = 0; t < 32; t++) {
        if (t + 1 < 32) {
            load_tile((t + 1) * 32, (t + 1) & 1);
            CP_COMMIT();
            CP_WAIT(1);
        } else {
            CP_WAIT(0);
        }
        __syncthreads();

        const float* Asb = smem + (t & 1) * GS_BUF;
        const float* Bsb = smem + (2 + (t & 1)) * GS_BUF;

        #pragma unroll
        for (int ks = 0; ks < 4; ks++) {
            const int kc = ks * 8 + gc;
            uint32_t a[4][4];
            #pragma unroll
            for (int mt = 0; mt < 4; mt++) {
                int r = wm * 64 + mt * 16 + gr;
                a[mt][0] = __float_as_uint(Asb[r * GS_ROW + kc]);
                a[mt][1] = __float_as_uint(Asb[(r + 8) * GS_ROW + kc]);
                a[mt][2] = __float_as_uint(Asb[r * GS_ROW + kc + 4]);
                a[mt][3] = __float_as_uint(Asb[(r + 8) * GS_ROW + kc + 4]);
            }
            uint32_t b[4][2];
            #pragma unroll
            for (int nt = 0; nt < 4; nt++) {
                int n = wn * 32 + nt * 8 + gr;
                b[nt][0] = __float_as_uint(Bsb[n * GS_ROW + kc]);
                b[nt][1] = __float_as_uint(Bsb[n * GS_ROW + kc + 4]);
            }
            #pragma unroll
            for (int mt = 0; mt < 4; mt++)
                #pragma unroll
                for (int nt = 0; nt < 4; nt++)
                    mma_tf32(d[mt][nt][0], d[mt][nt][1], d[mt][nt][2], d[mt][nt][3],
                             a[mt][0], a[mt][1], a[mt][2], a[mt][3],
                             b[nt][0], b[nt][1]);
        }
        __syncthreads();
    }

    // epilogue: bias add; tf32-round for head_layout (consumed by tf32 mma later)
    #pragma unroll
    for (int mt = 0; mt < 4; mt++) {
        int row = m0 + wm * 64 + mt * 16 + gr;
        #pragma unroll
        for (int nt = 0; nt < 4; nt++) {
            int col = n0 + wn * 32 + nt * 8 + 2 * gc;
            float2 bv = *(const float2*)&bias[col];
            float2 v0 = make_float2(d[mt][nt][0] + bv.x, d[mt][nt][1] + bv.y);
            float2 v1 = make_float2(d[mt][nt][2] + bv.x, d[mt][nt][3] + bv.y);
            if (head_layout) {
                v0.x = tf32r(v0.x); v0.y = tf32r(v0.y);
                v1.x = tf32r(v1.x); v1.y = tf32r(v1.y);
                int h = col >> 6, dd = col & 63;
                int b0_ = row >> 11, s0 = row & 2047;
                int b1_ = (row + 8) >> 11, s1 = (row + 8) & 2047;
                *(float2*)&out[(((size_t)(b0_ * NUM_HEADS + h) * SEQ) + s0) * HEAD_DIM + dd] = v0;
                *(float2*)&out[(((size_t)(b1_ * NUM_HEADS + h) * SEQ) + s1) * HEAD_DIM + dd] = v1;
            } else {
                *(float2*)&out[(size_t)row * D_MODEL + col] = v0;
                *(float2*)&out[(size_t)(row + 8) * D_MODEL + col] = v1;
            }
        }
    }
}

// ======================= MMA flash attention =======================
// CTA: 128 q-rows x sweep over K in 64-tiles. 8 warps, each 16 q-rows.
// Smem (floats): Ks[2][64][68], Vs[2][64][72], Ps[8][16][68]
#define KS_STR 68
#define KS_BUF (64 * KS_STR)         // 4352
#define VS_STR 72
#define VS_BUF (64 * VS_STR)         // 4608
#define VS_OFF (2 * KS_BUF)          // 8704
#define PS_OFF (VS_OFF + 2 * VS_BUF) // 17920
#define PS_WRP (16 * KS_STR)         // 1088
#define FLASH_SMEM ((PS_OFF + 8 * PS_WRP) * 4)   // 106496 bytes

__global__ __launch_bounds__(256, 1) void flash_mma(
    const float* __restrict__ Q, const float* __restrict__ K,
    const float* __restrict__ V, float* __restrict__ O)
{
    extern __shared__ __align__(16) float smf[];
    const uint32_t sbase = smem_u32(smf);

    const int tid  = threadIdx.x;
    const int lane = tid & 31;
    const int wid  = tid >> 5;
    const int gr   = lane >> 2;
    const int gc   = lane & 3;
    const int bh   = blockIdx.y;
    const int b_   = bh >> 4;
    const int h    = bh & 15;
    const int q0   = blockIdx.x * 128;

    const float* Qb = Q + (size_t)bh * SEQ * HEAD_DIM;
    const float* Kb = K + (size_t)bh * SEQ * HEAD_DIM;
    const float* Vb = V + (size_t)bh * SEQ * HEAD_DIM;

    // Q fragments, pre-scaled by 1/sqrt(64) * log2(e) (base-2 softmax domain)
    const float QSCALE = 0.125f * 1.44269504088896f;
    const int r0 = q0 + wid * 16 + gr;
    uint32_t q[8][4];
    #pragma unroll
    for (int ks = 0; ks < 8; ks++) {
        q[ks][0] = __float_as_uint(tf32r(Qb[(size_t)r0 * 64 + ks * 8 + gc] * QSCALE));
        q[ks][1] = __float_as_uint(tf32r(Qb[(size_t)(r0 + 8) * 64 + ks * 8 + gc] * QSCALE));
        q[ks][2] = __float_as_uint(tf32r(Qb[(size_t)r0 * 64 + ks * 8 + gc + 4] * QSCALE));
        q[ks][3] = __float_as_uint(tf32r(Qb[(size_t)(r0 + 8) * 64 + ks * 8 + gc + 4] * QSCALE));
    }

    float o[8][4];
    #pragma unroll
    for (int nt = 0; nt < 8; nt++)
        #pragma unroll
        for (int j = 0; j < 4; j++) o[nt][j] = 0.f;
    float m0r = -1e30f, m1r = -1e30f, l0 = 0.f, l1 = 0.f;

    // async load of one K/V 64x64 tile pair into buffer buf
    auto load_kv = [&](int k0, int buf) {
        #pragma unroll
        for (int it = 0; it < 4; it++) {
            int id = tid + it * 256;
            int r  = id >> 4;
            int c4 = (id & 15) * 4;
            cp16(sbase + (uint32_t)(buf * KS_BUF + r * KS_STR + c4) * 4u,
                 Kb + (size_t)(k0 + r) * 64 + c4);
            cp16(sbase + (uint32_t)(VS_OFF + buf * VS_BUF + r * VS_STR + c4) * 4u,
                 Vb + (size_t)(k0 + r) * 64 + c4);
        }
    };

    load_kv(0, 0);
    CP_COMMIT();

    float* Pw = smf + PS_OFF + wid * PS_WRP;

    #pragma unroll 1
    for (int t = 0; t < 32; t++) {
        if (t + 1 < 32) {
            load_kv((t + 1) * 64, (t + 1) & 1);
            CP_COMMIT();
            CP_WAIT(1);
        } else {
            CP_WAIT(0);
        }
        __syncthreads();

        const float* Ksb = smf + (t & 1) * KS_BUF;
        const float* Vsb = smf + VS_OFF + (t & 1) * VS_BUF;

        // ---- S = Q @ K^T (16x64 per warp) ----
        float s[8][4];
        #pragma unroll
        for (int nt = 0; nt < 8; nt++) {
            s[nt][0] = s[nt][1] = s[nt][2] = s[nt][3] = 0.f;
            #pragma unroll
            for (int ks = 0; ks < 8; ks++) {
                uint32_t b0 = __float_as_uint(Ksb[(nt * 8 + gr) * KS_STR + ks * 8 + gc]);
                uint32_t b1 = __float_as_uint(Ksb[(nt * 8 + gr) * KS_STR + ks * 8 + gc + 4]);
                mma_tf32(s[nt][0], s[nt][1], s[nt][2], s[nt][3],
                         q[ks][0], q[ks][1], q[ks][2], q[ks][3], b0, b1);
            }
        }

        // ---- online softmax (base-2) ----
        float mx0 = -1e30f, mx1 = -1e30f;
        #pragma unroll
        for (int nt = 0; nt < 8; nt++) {
            mx0 = fmaxf(mx0, fmaxf(s[nt][0], s[nt][1]));
            mx1 = fmaxf(mx1, fmaxf(s[nt][2], s[nt][3]));
        }
        mx0 = fmaxf(mx0, __shfl_xor_sync(0xffffffffu, mx0, 1));
        mx0 = fmaxf(mx0, __shfl_xor_sync(0xffffffffu, mx0, 2));
        mx1 = fmaxf(mx1, __shfl_xor_sync(0xffffffffu, mx1, 1));
        mx1 = fmaxf(mx1, __shfl_xor_sync(0xffffffffu, mx1, 2));

        float mn0 = fmaxf(m0r, mx0), mn1 = fmaxf(m1r, mx1);
        float a0 = exp2a(m0r - mn0), a1 = exp2a(m1r - mn1);
        m0r = mn0; m1r = mn1;

        float ls0 = 0.f, ls1 = 0.f;
        #pragma unroll
        for (int nt = 0; nt < 8; nt++) {
            s[nt][0] = tf32r(exp2a(s[nt][0] - mn0));
            s[nt][1] = tf32r(exp2a(s[nt][1] - mn0));
            s[nt][2] = tf32r(exp2a(s[nt][2] - mn1));
            s[nt][3] = tf32r(exp2a(s[nt][3] - mn1));
            ls0 += s[nt][0] + s[nt][1];
            ls1 += s[nt][2] + s[nt][3];
        }
        l0 = l0 * a0 + ls0;
        l1 = l1 * a1 + ls1;
        #pragma unroll
        for (int nt = 0; nt < 8; nt++) {
            o[nt][0] *= a0; o[nt][1] *= a0;
            o[nt][2] *= a1; o[nt][3] *= a1;
        }

        // ---- P -> smem (accumulator layout), re-read as A fragments ----
        #pragma unroll
        for (int nt = 0; nt < 8; nt++) {
            *(float2*)&Pw[gr * KS_STR + nt * 8 + 2 * gc]       = make_float2(s[nt][0], s[nt][1]);
            *(float2*)&Pw[(gr + 8) * KS_STR + nt * 8 + 2 * gc] = make_float2(s[nt][2], s[nt][3]);
        }
        __syncwarp();

        // ---- O += P @ V ----
        #pragma unroll
        for (int ks = 0; ks < 8; ks++) {
            uint32_t pa0 = __float_as_uint(Pw[gr * KS_STR + ks * 8 + gc]);
            uint32_t pa1 = __float_as_uint(Pw[(gr + 8) * KS_STR + ks * 8 + gc]);
            uint32_t pa2 = __float_as_uint(Pw[gr * KS_STR + ks * 8 + gc + 4]);
            uint32_t pa3 = __float_as_uint(Pw[(gr + 8) * KS_STR + ks * 8 + gc + 4]);
            #pragma unroll
            for (int nt = 0; nt < 8; nt++) {
                uint32_t b0 = __float_as_uint(Vsb[(ks * 8 + gc) * VS_STR + nt * 8 + gr]);
                uint32_t b1 = __float_as_uint(Vsb[(ks * 8 + gc + 4) * VS_STR + nt * 8 + gr]);
                mma_tf32(o[nt][0], o[nt][1], o[nt][2], o[nt][3],
                         pa0, pa1, pa2, pa3, b0, b1);
            }
        }
        __syncthreads();
    }

    // ---- finalize: reduce l over quad, divide, write tf32-rounded ----
    l0 += __shfl_xor_sync(0xffffffffu, l0, 1);
    l0 += __shfl_xor_sync(0xffffffffu, l0, 2);
    l1 += __shfl_xor_sync(0xffffffffu, l1, 1);
    l1 += __shfl_xor_sync(0xffffffffu, l1, 2);
    float inv0 = 1.f / l0, inv1 = 1.f / l1;

    #pragma unroll
    for (int nt = 0; nt < 8; nt++) {
        int col = h * 64 + nt * 8 + 2 * gc;
        float2 v0 = make_float2(tf32r(o[nt][0] * inv0), tf32r(o[nt][1] * inv0));
        float2 v1 = make_float2(tf32r(o[nt][2] * inv1), tf32r(o[nt][3] * inv1));
        *(float2*)&O[(size_t)(b_ * SEQ + r0) * D_MODEL + col] = v0;
        *(float2*)&O[(size_t)(b_ * SEQ + r0 + 8) * D_MODEL + col] = v1;
    }
}

// ======================= launcher =======================
extern "C" void kernel_launch(void* const* d_in, const int* in_sizes, int n_in,
                              void* d_out, int out_size)
{
    const float* x  = (const float*)d_in[0];
    const float* Wq = (const float*)d_in[1];
    const float* bq = (const float*)d_in[2];
    const float* Wk = (const float*)d_in[3];
    const float* bk = (const float*)d_in[4];
    const float* Wv = (const float*)d_in[5];
    const float* bv = (const float*)d_in[6];
    const float* Wo = (const float*)d_in[7];
    const float* bo = (const float*)d_in[8];
    float* out = (float*)d_out;

    static float *pq, *pk, *pv, *pao, *pxt, *pwq, *pwk, *pwv, *pwo;
    static bool inited = false;
    if (!inited) {
        cudaGetSymbolAddress((void**)&pq,  g_q);
        cudaGetSymbolAddress((void**)&pk,  g_k);
        cudaGetSymbolAddress((void**)&pv,  g_v);
        cudaGetSymbolAddress((void**)&pao, g_ao);
        cudaGetSymbolAddress((void**)&pxt, g_xt);
        cudaGetSymbolAddress((void**)&pwq, g_wq);
        cudaGetSymbolAddress((void**)&pwk, g_wk);
        cudaGetSymbolAddress((void**)&pwv, g_wv);
        cudaGetSymbolAddress((void**)&pwo, g_wo);
        cudaFuncSetAttribute(gemm_mma,
                             cudaFuncAttributeMaxDynamicSharedMemorySize, GEMM_SMEM);
        cudaFuncSetAttribute(flash_mma,
                             cudaFuncAttributeMaxDynamicSharedMemorySize, FLASH_SMEM);
        inited = true;
    }

    // tf32 round-convert X and the four weight matrices
    {
        int n4x = M_TOT * D_MODEL / 4;
        int n4w = D_MODEL * D_MODEL / 4;
        cvt_tf32<<<(n4x + 255) / 256, 256>>>((const float4*)x,  (float4*)pxt, n4x);
        cvt_tf32<<<(n4w + 255) / 256, 256>>>((const float4*)Wq, (float4*)pwq, n4w);
        cvt_tf32<<<(n4w + 255) / 256, 256>>>((const float4*)Wk, (float4*)pwk, n4w);
        cvt_tf32<<<(n4w + 255) / 256, 256>>>((const float4*)Wv, (float4*)pwv, n4w);
        cvt_tf32<<<(n4w + 255) / 256, 256>>>((const float4*)Wo, (float4*)pwo, n4w);
    }

    dim3 ggrid(D_MODEL / 128, M_TOT / 128);   // (8, 32)
    gemm_mma<<<ggrid, 256, GEMM_SMEM>>>(pxt, pwq, bq, pq, 1);
    gemm_mma<<<ggrid, 256, GEMM_SMEM>>>(pxt, pwk, bk, pk, 1);
    gemm_mma<<<ggrid, 256, GEMM_SMEM>>>(pxt, pwv, bv, pv, 1);

    dim3 agrid(SEQ / 128, BATCH * NUM_HEADS);  // (16, 32)
    flash_mma<<<agrid, 256, FLASH_SMEM>>>(pq, pk, pv, pao);

    gemm_mma<<<ggrid, 256, GEMM_SMEM>>>(pao, pwo, bo, out, 0);
}

// round 5
// speedup vs baseline: 4.7030x; 1.0545x over previous
#include <cuda_runtime.h>
#include <math.h>
#include <stdint.h>

#define D_MODEL   1024
#define NUM_HEADS 16
#define HEAD_DIM  64
#define BATCH     2
#define SEQ       2048
#define M_TOT     (BATCH * SEQ)   // 4096

// ---------------- scratch (device globals; no allocation) ----------------
__device__ float g_q [BATCH * NUM_HEADS * SEQ * HEAD_DIM];   // 16 MB (tf32)
__device__ float g_k [BATCH * NUM_HEADS * SEQ * HEAD_DIM];   // 16 MB (tf32)
__device__ float g_v [BATCH * NUM_HEADS * SEQ * HEAD_DIM];   // 16 MB (tf32)
__device__ float g_ao[M_TOT * D_MODEL];                      // 16 MB (tf32)
__device__ float g_xt[M_TOT * D_MODEL];                      // 16 MB x in tf32
__device__ float g_wq[D_MODEL * D_MODEL];                    // 4 MB each
__device__ float g_wk[D_MODEL * D_MODEL];
__device__ float g_wv[D_MODEL * D_MODEL];
__device__ float g_wo[D_MODEL * D_MODEL];

// ======================= helpers =======================
static __device__ __forceinline__ uint32_t smem_u32(const void* p) {
    uint32_t a;
    asm("{ .reg .u64 t; cvta.to.shared.u64 t, %1; cvt.u32.u64 %0, t; }"
        : "=r"(a) : "l"(p));
    return a;
}
static __device__ __forceinline__ float tf32r(float x) {
    uint32_t u;
    asm("cvt.rna.tf32.f32 %0, %1;" : "=r"(u) : "f"(x));
    return __uint_as_float(u);
}
static __device__ __forceinline__ float exp2a(float x) {
    float y;
    asm("ex2.approx.ftz.f32 %0, %1;" : "=f"(y) : "f"(x));
    return y;
}
static __device__ __forceinline__ void cp16(uint32_t dst, const void* src) {
    asm volatile("cp.async.ca.shared.global [%0], [%1], 16;"
                 :: "r"(dst), "l"(src) : "memory");
}
#define CP_COMMIT() asm volatile("cp.async.commit_group;" ::: "memory")
#define CP_WAIT(n)  asm volatile("cp.async.wait_group %0;" :: "n"(n) : "memory")

static __device__ __forceinline__ void mma_tf32(
    float& d0, float& d1, float& d2, float& d3,
    uint32_t a0, uint32_t a1, uint32_t a2, uint32_t a3,
    uint32_t b0, uint32_t b1)
{
    asm volatile(
        "mma.sync.aligned.m16n8k8.row.col.f32.tf32.tf32.f32 "
        "{%0,%1,%2,%3}, {%4,%5,%6,%7}, {%8,%9}, {%0,%1,%2,%3};"
        : "+f"(d0), "+f"(d1), "+f"(d2), "+f"(d3)
        : "r"(a0), "r"(a1), "r"(a2), "r"(a3), "r"(b0), "r"(b1));
}

// ======================= tf32 round-convert =======================
__global__ __launch_bounds__(256) void cvt_tf32(
    const float4* __restrict__ in, float4* __restrict__ out, int n4)
{
    int i = blockIdx.x * 256 + threadIdx.x;
    if (i < n4) {
        float4 v = in[i];
        v.x = tf32r(v.x); v.y = tf32r(v.y); v.z = tf32r(v.z); v.w = tf32r(v.w);
        out[i] = v;
    }
}

// all four 1024x1024 weights in one launch: segment = blockIdx.x >> 10
__global__ __launch_bounds__(256) void cvt_tf32_w4(
    const float4* __restrict__ w0, const float4* __restrict__ w1,
    const float4* __restrict__ w2, const float4* __restrict__ w3,
    float4* __restrict__ o0, float4* __restrict__ o1,
    float4* __restrict__ o2, float4* __restrict__ o3)
{
    const int seg = blockIdx.x >> 10;            // 1024 blocks per 256K-float4 segment
    const int i   = (blockIdx.x & 1023) * 256 + threadIdx.x;
    const float4* in  = (seg == 0) ? w0 : (seg == 1) ? w1 : (seg == 2) ? w2 : w3;
    float4*       out = (seg == 0) ? o0 : (seg == 1) ? o1 : (seg == 2) ? o2 : o3;
    float4 v = in[i];
    v.x = tf32r(v.x); v.y = tf32r(v.y); v.z = tf32r(v.z); v.w = tf32r(v.w);
    out[i] = v;
}

// ======================= mma.sync tf32 GEMM (device core) =======================
#define GS_ROW   36
#define GS_BUF   (128 * GS_ROW)
#define GEMM_SMEM (4 * GS_BUF * 4)           // 73728 bytes

static __device__ __forceinline__ void gemm_core(
    const float* __restrict__ A, const float* __restrict__ B,
    const float* __restrict__ bias, float* __restrict__ out,
    int m0, int n0, int head_layout, float* smem, uint32_t sbase)
{
    const int tid  = threadIdx.x;
    const int lane = tid & 31;
    const int wid  = tid >> 5;
    const int wm   = wid & 1;
    const int wn   = wid >> 1;
    const int gr   = lane >> 2;
    const int gc   = lane & 3;

    float d[4][4][4];
    #pragma unroll
    for (int mt = 0; mt < 4; mt++)
        #pragma unroll
        for (int nt = 0; nt < 4; nt++)
            #pragma unroll
            for (int r = 0; r < 4; r++) d[mt][nt][r] = 0.f;

    auto load_tile = [&](int kt, int buf) {
        #pragma unroll
        for (int it = 0; it < 4; it++) {
            int id = tid + it * 256;
            int r  = id >> 3;
            int ch = (id & 7) * 4;
            uint32_t da = sbase + (uint32_t)(buf * GS_BUF + r * GS_ROW + ch) * 4u;
            cp16(da, A + (size_t)(m0 + r) * D_MODEL + kt + ch);
            uint32_t db = sbase + (uint32_t)((2 + buf) * GS_BUF + r * GS_ROW + ch) * 4u;
            cp16(db, B + (size_t)(n0 + r) * D_MODEL + kt + ch);
        }
    };

    load_tile(0, 0);
    CP_COMMIT();

    for (int t = 0; t < 32; t++) {
        if (t + 1 < 32) {
            load_tile((t + 1) * 32, (t + 1) & 1);
            CP_COMMIT();
            CP_WAIT(1);
        } else {
            CP_WAIT(0);
        }
        __syncthreads();

        const float* Asb = smem + (t & 1) * GS_BUF;
        const float* Bsb = smem + (2 + (t & 1)) * GS_BUF;

        #pragma unroll
        for (int ks = 0; ks < 4; ks++) {
            const int kc = ks * 8 + gc;
            uint32_t a[4][4];
            #pragma unroll
            for (int mt = 0; mt < 4; mt++) {
                int r = wm * 64 + mt * 16 + gr;
                a[mt][0] = __float_as_uint(Asb[r * GS_ROW + kc]);
                a[mt][1] = __float_as_uint(Asb[(r + 8) * GS_ROW + kc]);
                a[mt][2] = __float_as_uint(Asb[r * GS_ROW + kc + 4]);
                a[mt][3] = __float_as_uint(Asb[(r + 8) * GS_ROW + kc + 4]);
            }
            uint32_t b[4][2];
            #pragma unroll
            for (int nt = 0; nt < 4; nt++) {
                int n = wn * 32 + nt * 8 + gr;
                b[nt][0] = __float_as_uint(Bsb[n * GS_ROW + kc]);
                b[nt][1] = __float_as_uint(Bsb[n * GS_ROW + kc + 4]);
            }
            #pragma unroll
            for (int mt = 0; mt < 4; mt++)
                #pragma unroll
                for (int nt = 0; nt < 4; nt++)
                    mma_tf32(d[mt][nt][0], d[mt][nt][1], d[mt][nt][2], d[mt][nt][3],
                             a[mt][0], a[mt][1], a[mt][2], a[mt][3],
                             b[nt][0], b[nt][1]);
        }
        __syncthreads();
    }

    #pragma unroll
    for (int mt = 0; mt < 4; mt++) {
        int row = m0 + wm * 64 + mt * 16 + gr;
        #pragma unroll
        for (int nt = 0; nt < 4; nt++) {
            int col = n0 + wn * 32 + nt * 8 + 2 * gc;
            int colw = col & 1023;
            float2 bv = *(const float2*)&bias[colw];
            float2 v0 = make_float2(d[mt][nt][0] + bv.x, d[mt][nt][1] + bv.y);
            float2 v1 = make_float2(d[mt][nt][2] + bv.x, d[mt][nt][3] + bv.y);
            if (head_layout) {
                v0.x = tf32r(v0.x); v0.y = tf32r(v0.y);
                v1.x = tf32r(v1.x); v1.y = tf32r(v1.y);
                int h = colw >> 6, dd = colw & 63;
                int b0_ = row >> 11, s0 = row & 2047;
                int b1_ = (row + 8) >> 11, s1 = (row + 8) & 2047;
                *(float2*)&out[(((size_t)(b0_ * NUM_HEADS + h) * SEQ) + s0) * HEAD_DIM + dd] = v0;
                *(float2*)&out[(((size_t)(b1_ * NUM_HEADS + h) * SEQ) + s1) * HEAD_DIM + dd] = v1;
            } else {
                *(float2*)&out[(size_t)row * D_MODEL + colw] = v0;
                *(float2*)&out[(size_t)(row + 8) * D_MODEL + colw] = v1;
            }
        }
    }
}

// fused QKV: grid (24, 32); blockIdx.x>>3 selects {Wq->q, Wk->k, Wv->v}
__global__ __launch_bounds__(256, 2) void gemm_qkv(
    const float* __restrict__ X,
    const float* __restrict__ Wq, const float* __restrict__ Wk, const float* __restrict__ Wv,
    const float* __restrict__ bq, const float* __restrict__ bk, const float* __restrict__ bv,
    float* __restrict__ oq, float* __restrict__ ok, float* __restrict__ ov)
{
    extern __shared__ __align__(16) float smem[];
    const uint32_t sbase = smem_u32(smem);
    const int which = blockIdx.x >> 3;
    const float* W = (which == 0) ? Wq : (which == 1) ? Wk : Wv;
    const float* bias = (which == 0) ? bq : (which == 1) ? bk : bv;
    float* out = (which == 0) ? oq : (which == 1) ? ok : ov;
    gemm_core(X, W, bias, out, blockIdx.y * 128, (blockIdx.x & 7) * 128, 1, smem, sbase);
}

__global__ __launch_bounds__(256, 2) void gemm_mma(
    const float* __restrict__ A, const float* __restrict__ B,
    const float* __restrict__ bias, float* __restrict__ out, int head_layout)
{
    extern __shared__ __align__(16) float smem[];
    const uint32_t sbase = smem_u32(smem);
    gemm_core(A, B, bias, out, blockIdx.y * 128, blockIdx.x * 128, head_layout, smem, sbase);
}

// ======================= MMA flash attention =======================
// CTA: 128 q-rows x sweep over K in 64-tiles. 8 warps, each 16 q-rows. occ=2.
#define KS_STR 68
#define KS_BUF (64 * KS_STR)         // 4352
#define VS_STR 72
#define VS_BUF (64 * VS_STR)         // 4608
#define VS_OFF (2 * KS_BUF)          // 8704
#define PS_OFF (VS_OFF + 2 * VS_BUF) // 17920
#define PS_WRP (16 * KS_STR)         // 1088
#define FLASH_SMEM ((PS_OFF + 8 * PS_WRP) * 4)   // 106496 bytes (2/SM fits 228KB)

__global__ __launch_bounds__(256, 2) void flash_mma(
    const float* __restrict__ Q, const float* __restrict__ K,
    const float* __restrict__ V, float* __restrict__ O)
{
    extern __shared__ __align__(16) float smf[];
    const uint32_t sbase = smem_u32(smf);

    const int tid  = threadIdx.x;
    const int lane = tid & 31;
    const int wid  = tid >> 5;
    const int gr   = lane >> 2;
    const int gc   = lane & 3;
    const int bh   = blockIdx.y;
    const int b_   = bh >> 4;
    const int h    = bh & 15;
    const int q0   = blockIdx.x * 128;

    const float* Qb = Q + (size_t)bh * SEQ * HEAD_DIM;
    const float* Kb = K + (size_t)bh * SEQ * HEAD_DIM;
    const float* Vb = V + (size_t)bh * SEQ * HEAD_DIM;

    const float QSCALE = 0.125f * 1.44269504088896f;  // 1/sqrt(64) * log2(e)
    const int r0 = q0 + wid * 16 + gr;
    uint32_t q[8][4];
    #pragma unroll
    for (int ks = 0; ks < 8; ks++) {
        q[ks][0] = __float_as_uint(tf32r(Qb[(size_t)r0 * 64 + ks * 8 + gc] * QSCALE));
        q[ks][1] = __float_as_uint(tf32r(Qb[(size_t)(r0 + 8) * 64 + ks * 8 + gc] * QSCALE));
        q[ks][2] = __float_as_uint(tf32r(Qb[(size_t)r0 * 64 + ks * 8 + gc + 4] * QSCALE));
        q[ks][3] = __float_as_uint(tf32r(Qb[(size_t)(r0 + 8) * 64 + ks * 8 + gc + 4] * QSCALE));
    }

    float o[8][4];
    #pragma unroll
    for (int nt = 0; nt < 8; nt++)
        #pragma unroll
        for (int j = 0; j < 4; j++) o[nt][j] = 0.f;
    float m0r = -1e30f, m1r = -1e30f, l0 = 0.f, l1 = 0.f;

    auto load_kv = [&](int k0, int buf) {
        #pragma unroll
        for (int it = 0; it < 4; it++) {
            int id = tid + it * 256;
            int r  = id >> 4;
            int c4 = (id & 15) * 4;
            cp16(sbase + (uint32_t)(buf * KS_BUF + r * KS_STR + c4) * 4u,
                 Kb + (size_t)(k0 + r) * 64 + c4);
            cp16(sbase + (uint32_t)(VS_OFF + buf * VS_BUF + r * VS_STR + c4) * 4u,
                 Vb + (size_t)(k0 + r) * 64 + c4);
        }
    };

    load_kv(0, 0);
    CP_COMMIT();

    float* Pw = smf + PS_OFF + wid * PS_WRP;

    #pragma unroll 1
    for (int t = 0; t < 32; t++) {
        if (t + 1 < 32) {
            load_kv((t + 1) * 64, (t + 1) & 1);
            CP_COMMIT();
            CP_WAIT(1);
        } else {
            CP_WAIT(0);
        }
        __syncthreads();

        const float* Ksb = smf + (t & 1) * KS_BUF;
        const float* Vsb = smf + VS_OFF + (t & 1) * VS_BUF;

        // ---- S = Q @ K^T ----
        float s[8][4];
        #pragma unroll
        for (int nt = 0; nt < 8; nt++) {
            s[nt][0] = s[nt][1] = s[nt][2] = s[nt][3] = 0.f;
            #pragma unroll
            for (int ks = 0; ks < 8; ks++) {
                uint32_t b0 = __float_as_uint(Ksb[(nt * 8 + gr) * KS_STR + ks * 8 + gc]);
                uint32_t b1 = __float_as_uint(Ksb[(nt * 8 + gr) * KS_STR + ks * 8 + gc + 4]);
                mma_tf32(s[nt][0], s[nt][1], s[nt][2], s[nt][3],
                         q[ks][0], q[ks][1], q[ks][2], q[ks][3], b0, b1);
            }
        }

        // ---- online softmax (base-2) ----
        float mx0 = -1e30f, mx1 = -1e30f;
        #pragma unroll
        for (int nt = 0; nt < 8; nt++) {
            mx0 = fmaxf(mx0, fmaxf(s[nt][0], s[nt][1]));
            mx1 = fmaxf(mx1, fmaxf(s[nt][2], s[nt][3]));
        }
        mx0 = fmaxf(mx0, __shfl_xor_sync(0xffffffffu, mx0, 1));
        mx0 = fmaxf(mx0, __shfl_xor_sync(0xffffffffu, mx0, 2));
        mx1 = fmaxf(mx1, __shfl_xor_sync(0xffffffffu, mx1, 1));
        mx1 = fmaxf(mx1, __shfl_xor_sync(0xffffffffu, mx1, 2));

        float mn0 = fmaxf(m0r, mx0), mn1 = fmaxf(m1r, mx1);
        float a0 = exp2a(m0r - mn0), a1 = exp2a(m1r - mn1);
        m0r = mn0; m1r = mn1;

        float ls0 = 0.f, ls1 = 0.f;
        #pragma unroll
        for (int nt = 0; nt < 8; nt++) {
            s[nt][0] = tf32r(exp2a(s[nt][0] - mn0));
            s[nt][1] = tf32r(exp2a(s[nt][1] - mn0));
            s[nt][2] = tf32r(exp2a(s[nt][2] - mn1));
            s[nt][3] = tf32r(exp2a(s[nt][3] - mn1));
            ls0 += s[nt][0] + s[nt][1];
            ls1 += s[nt][2] + s[nt][3];
        }
        l0 = l0 * a0 + ls0;
        l1 = l1 * a1 + ls1;
        #pragma unroll
        for (int nt = 0; nt < 8; nt++) {
            o[nt][0] *= a0; o[nt][1] *= a0;
            o[nt][2] *= a1; o[nt][3] *= a1;
        }

        // ---- P -> smem, re-read as A fragments ----
        #pragma unroll
        for (int nt = 0; nt < 8; nt++) {
            *(float2*)&Pw[gr * KS_STR + nt * 8 + 2 * gc]       = make_float2(s[nt][0], s[nt][1]);
            *(float2*)&Pw[(gr + 8) * KS_STR + nt * 8 + 2 * gc] = make_float2(s[nt][2], s[nt][3]);
        }
        __syncwarp();

        // ---- O += P @ V ----
        #pragma unroll
        for (int ks = 0; ks < 8; ks++) {
            uint32_t pa0 = __float_as_uint(Pw[gr * KS_STR + ks * 8 + gc]);
            uint32_t pa1 = __float_as_uint(Pw[(gr + 8) * KS_STR + ks * 8 + gc]);
            uint32_t pa2 = __float_as_uint(Pw[gr * KS_STR + ks * 8 + gc + 4]);
            uint32_t pa3 = __float_as_uint(Pw[(gr + 8) * KS_STR + ks * 8 + gc + 4]);
            #pragma unroll
            for (int nt = 0; nt < 8; nt++) {
                uint32_t b0 = __float_as_uint(Vsb[(ks * 8 + gc) * VS_STR + nt * 8 + gr]);
                uint32_t b1 = __float_as_uint(Vsb[(ks * 8 + gc + 4) * VS_STR + nt * 8 + gr]);
                mma_tf32(o[nt][0], o[nt][1], o[nt][2], o[nt][3],
                         pa0, pa1, pa2, pa3, b0, b1);
            }
        }
        __syncthreads();
    }

    // ---- finalize ----
    l0 += __shfl_xor_sync(0xffffffffu, l0, 1);
    l0 += __shfl_xor_sync(0xffffffffu, l0, 2);
    l1 += __shfl_xor_sync(0xffffffffu, l1, 1);
    l1 += __shfl_xor_sync(0xffffffffu, l1, 2);
    float inv0 = 1.f / l0, inv1 = 1.f / l1;

    #pragma unroll
    for (int nt = 0; nt < 8; nt++) {
        int col = h * 64 + nt * 8 + 2 * gc;
        float2 v0 = make_float2(tf32r(o[nt][0] * inv0), tf32r(o[nt][1] * inv0));
        float2 v1 = make_float2(tf32r(o[nt][2] * inv1), tf32r(o[nt][3] * inv1));
        *(float2*)&O[(size_t)(b_ * SEQ + r0) * D_MODEL + col] = v0;
        *(float2*)&O[(size_t)(b_ * SEQ + r0 + 8) * D_MODEL + col] = v1;
    }
}

// ======================= launcher =======================
extern "C" void kernel_launch(void* const* d_in, const int* in_sizes, int n_in,
                              void* d_out, int out_size)
{
    const float* x  = (const float*)d_in[0];
    const float* Wq = (const float*)d_in[1];
    const float* bq = (const float*)d_in[2];
    const float* Wk = (const float*)d_in[3];
    const float* bk = (const float*)d_in[4];
    const float* Wv = (const float*)d_in[5];
    const float* bv = (const float*)d_in[6];
    const float* Wo = (const float*)d_in[7];
    const float* bo = (const float*)d_in[8];
    float* out = (float*)d_out;

    static float *pq, *pk, *pv, *pao, *pxt, *pwq, *pwk, *pwv, *pwo;
    static bool inited = false;
    if (!inited) {
        cudaGetSymbolAddress((void**)&pq,  g_q);
        cudaGetSymbolAddress((void**)&pk,  g_k);
        cudaGetSymbolAddress((void**)&pv,  g_v);
        cudaGetSymbolAddress((void**)&pao, g_ao);
        cudaGetSymbolAddress((void**)&pxt, g_xt);
        cudaGetSymbolAddress((void**)&pwq, g_wq);
        cudaGetSymbolAddress((void**)&pwk, g_wk);
        cudaGetSymbolAddress((void**)&pwv, g_wv);
        cudaGetSymbolAddress((void**)&pwo, g_wo);
        cudaFuncSetAttribute(gemm_mma,
                             cudaFuncAttributeMaxDynamicSharedMemorySize, GEMM_SMEM);
        cudaFuncSetAttribute(gemm_qkv,
                             cudaFuncAttributeMaxDynamicSharedMemorySize, GEMM_SMEM);
        cudaFuncSetAttribute(flash_mma,
                             cudaFuncAttributeMaxDynamicSharedMemorySize, FLASH_SMEM);
        inited = true;
    }

    // tf32 round-convert: x (one launch) + all 4 weights (one launch)
    {
        int n4x = M_TOT * D_MODEL / 4;
        cvt_tf32<<<(n4x + 255) / 256, 256>>>((const float4*)x, (float4*)pxt, n4x);
        cvt_tf32_w4<<<4096, 256>>>(
            (const float4*)Wq, (const float4*)Wk, (const float4*)Wv, (const float4*)Wo,
            (float4*)pwq, (float4*)pwk, (float4*)pwv, (float4*)pwo);
    }

    // fused QKV projections: one launch, 768 CTAs
    dim3 qgrid(24, M_TOT / 128);   // (24, 32)
    gemm_qkv<<<qgrid, 256, GEMM_SMEM>>>(pxt, pwq, pwk, pwv, bq, bk, bv, pq, pk, pv);

    dim3 agrid(SEQ / 128, BATCH * NUM_HEADS);  // (16, 32)
    flash_mma<<<agrid, 256, FLASH_SMEM>>>(pq, pk, pv, pao);

    dim3 ggrid(D_MODEL / 128, M_TOT / 128);    // (8, 32)
    gemm_mma<<<ggrid, 256, GEMM_SMEM>>>(pao, pwo, bo, out, 0);
}